// round 2
// baseline (speedup 1.0000x reference)
#include <cuda_runtime.h>
#include <cstdint>

// ---------------------------------------------------------------------------
// Problem constants (fixed shapes from reference)
// ---------------------------------------------------------------------------
constexpr int Bb = 2, Tt = 256, Mm = 80, Dd = 512;
constexpr int NT = Bb * Tt * Mm;   // 40960 tokens
constexpr int G3 = 3 * Dd;         // 1536
constexpr int NSEQ_T = Bb * Mm;    // 160 time-GRU sequences
constexpr int NSEQ_F = Bb * Tt;    // 512 freq-GRU sequences

// ---------------------------------------------------------------------------
// Scratch (static device memory; no runtime allocation allowed)
// ---------------------------------------------------------------------------
__device__ float g_gi_t[(size_t)NT * G3];   // time GRU input projections
__device__ float g_gi_f[(size_t)NT * G3];   // freq fwd GRU input projections
__device__ float g_gi_b[(size_t)NT * G3];   // freq bwd GRU input projections
__device__ float g_gi_s[(size_t)NT * G3];   // stack GRU input projections
__device__ float g_xcat[(size_t)NT * G3];   // concat(x1, fwd, bwd)
__device__ float g_xs[(size_t)NT * Dd];     // stack GRU outputs
__device__ float g_h0[NSEQ_F * Dd];         // hidden ping/pong buffers
__device__ float g_h1[NSEQ_F * Dd];
__device__ float g_h2[NSEQ_F * Dd];
__device__ float g_h3[NSEQ_F * Dd];

// ---------------------------------------------------------------------------
// Generic GEMM:  C[Mr,N] = (A (+A2))[Mr,K] @ W[N,K]^T + bias[N] (+ res[Mr,N])
// BM=128, BN=64, BK=16, 256 threads, 8x4 per-thread tile.
// Mr is implied by gridDim.y*128 (all our Mr = 40960, divisible).
// ---------------------------------------------------------------------------
__global__ __launch_bounds__(256) void gemm_tn(
    const float* __restrict__ A, const float* __restrict__ A2,
    const float* __restrict__ W, const float* __restrict__ bias,
    const float* __restrict__ res, float* __restrict__ C,
    int K, int N)
{
    __shared__ float As[16][132];  // [k][row], padded
    __shared__ float Ws[16][68];   // [k][col], padded

    const int tid = threadIdx.x;
    const int row0 = blockIdx.y * 128;
    const int col0 = blockIdx.x * 64;
    const int tx = tid & 15;   // 16 col groups * 4 cols
    const int ty = tid >> 4;   // 16 row groups * 8 rows

    float acc[8][4];
#pragma unroll
    for (int i = 0; i < 8; i++)
#pragma unroll
        for (int j = 0; j < 4; j++) acc[i][j] = 0.f;

    for (int k0 = 0; k0 < K; k0 += 16) {
        // load A tile (128x16), 2 float4 per thread, transpose into smem
#pragma unroll
        for (int i = 0; i < 2; i++) {
            int idx = tid * 2 + i;          // 0..511
            int r = idx >> 2;               // 0..127
            int c4 = (idx & 3) * 4;         // 0,4,8,12
            float4 v = *reinterpret_cast<const float4*>(
                A + (size_t)(row0 + r) * K + k0 + c4);
            if (A2) {
                float4 w = *reinterpret_cast<const float4*>(
                    A2 + (size_t)(row0 + r) * K + k0 + c4);
                v.x += w.x; v.y += w.y; v.z += w.z; v.w += w.w;
            }
            As[c4 + 0][r] = v.x; As[c4 + 1][r] = v.y;
            As[c4 + 2][r] = v.z; As[c4 + 3][r] = v.w;
        }
        // load W tile (64x16), 1 float4 per thread
        {
            int r = tid >> 2;               // 0..63
            int c4 = (tid & 3) * 4;
            float4 v = *reinterpret_cast<const float4*>(
                W + (size_t)(col0 + r) * K + k0 + c4);
            Ws[c4 + 0][r] = v.x; Ws[c4 + 1][r] = v.y;
            Ws[c4 + 2][r] = v.z; Ws[c4 + 3][r] = v.w;
        }
        __syncthreads();

#pragma unroll
        for (int kk = 0; kk < 16; kk++) {
            float a[8], b[4];
            *reinterpret_cast<float4*>(a) =
                *reinterpret_cast<const float4*>(&As[kk][ty * 8]);
            *reinterpret_cast<float4*>(a + 4) =
                *reinterpret_cast<const float4*>(&As[kk][ty * 8 + 4]);
            *reinterpret_cast<float4*>(b) =
                *reinterpret_cast<const float4*>(&Ws[kk][tx * 4]);
#pragma unroll
            for (int i = 0; i < 8; i++)
#pragma unroll
                for (int j = 0; j < 4; j++)
                    acc[i][j] += a[i] * b[j];
        }
        __syncthreads();
    }

#pragma unroll
    for (int i = 0; i < 8; i++) {
        int r = row0 + ty * 8 + i;
#pragma unroll
        for (int j = 0; j < 4; j++) {
            int c = col0 + tx * 4 + j;
            float v = acc[i][j] + bias[c];
            if (res) v += res[(size_t)r * N + c];
            C[(size_t)r * N + c] = v;
        }
    }
}

// ---------------------------------------------------------------------------
// Fused GRU step: gh = h_prev @ W_hh^T (for this block's 32 hidden cols x 3
// gates), then gate nonlinearity + hidden update + output write.
// Block: TS sequences x 32 hidden cols x 3 gates. 256 threads = 8 warps;
// warp w owns sequences [w*SPW, (w+1)*SPW), lane = hidden col within tile.
// gridDim.z selects S0/S1 (used to fuse fwd+bwd freq GRUs in one launch).
// ---------------------------------------------------------------------------
struct GruSet {
    const float* hprev;
    float*       hnext;
    const float* gi;     // (NT, 1536)
    const float* Whh;    // (1536, 512)
    const float* bhh;    // (1536,)
    float*       out;    // output tensor
    int outStride;       // row stride of out
    int outOff;          // column offset within out row
    int mtok;            // m index for freq-mode token computation
};

__device__ __forceinline__ float sigf(float x) {
    return 1.f / (1.f + __expf(-x));
}
__device__ __forceinline__ float tanhfast(float x) {
    // 1 - 2/(e^{2x}+1); saturates correctly at +-1 for |x| large
    float e2x = __expf(2.f * x);
    return 1.f - 2.f / (e2x + 1.f);
}

template <int TS, bool TIME>
__global__ __launch_bounds__(256) void gru_step(GruSet S0, GruSet S1, int t)
{
    const GruSet S = (blockIdx.z == 0) ? S0 : S1;
    constexpr int SPW = TS / 8;  // sequences per warp

    __shared__ float Hs[TS][33];
    __shared__ float Ws[3][32][33];

    const int tid = threadIdx.x;
    const int lane = tid & 31;
    const int warp = tid >> 5;
    const int s0 = blockIdx.x * TS;
    const int j0 = blockIdx.y * 32;

    float accR[SPW], accZ[SPW], accN[SPW];
#pragma unroll
    for (int u = 0; u < SPW; u++) { accR[u] = 0.f; accZ[u] = 0.f; accN[u] = 0.f; }

    for (int k0 = 0; k0 < 512; k0 += 32) {
        // load H tile: TS x 32
        if (tid < TS * 8) {
            int ss = tid >> 3;
            int c4 = (tid & 7) * 4;
            float4 v = *reinterpret_cast<const float4*>(
                S.hprev + (size_t)(s0 + ss) * 512 + k0 + c4);
            Hs[ss][c4 + 0] = v.x; Hs[ss][c4 + 1] = v.y;
            Hs[ss][c4 + 2] = v.z; Hs[ss][c4 + 3] = v.w;
        }
        // load W tiles for the 3 gates: 3 x 32 x 32
        {
            int jj = tid >> 3;
            int c4 = (tid & 7) * 4;
#pragma unroll
            for (int g = 0; g < 3; g++) {
                float4 v = *reinterpret_cast<const float4*>(
                    S.Whh + (size_t)(g * 512 + j0 + jj) * 512 + k0 + c4);
                Ws[g][jj][c4 + 0] = v.x; Ws[g][jj][c4 + 1] = v.y;
                Ws[g][jj][c4 + 2] = v.z; Ws[g][jj][c4 + 3] = v.w;
            }
        }
        __syncthreads();

#pragma unroll
        for (int kk = 0; kk < 32; kk++) {
            float wr = Ws[0][lane][kk];
            float wz = Ws[1][lane][kk];
            float wn = Ws[2][lane][kk];
#pragma unroll
            for (int u = 0; u < SPW; u++) {
                float hv = Hs[warp * SPW + u][kk];
                accR[u] += hv * wr;
                accZ[u] += hv * wz;
                accN[u] += hv * wn;
            }
        }
        __syncthreads();
    }

    const int jc = j0 + lane;
    const float br = S.bhh[jc];
    const float bz = S.bhh[512 + jc];
    const float bn = S.bhh[1024 + jc];

#pragma unroll
    for (int u = 0; u < SPW; u++) {
        int s = s0 + warp * SPW + u;
        int token;
        if (TIME) {
            int b = s / Mm;
            int m = s - b * Mm;
            token = (b * Tt + t) * Mm + m;
        } else {
            token = s * Mm + S.mtok;
        }
        const float* gir = S.gi + (size_t)token * G3;
        float r = sigf(gir[jc] + accR[u] + br);
        float z = sigf(gir[512 + jc] + accZ[u] + bz);
        float n = tanhfast(gir[1024 + jc] + r * (accN[u] + bn));
        float hp = S.hprev[(size_t)s * 512 + jc];
        float hn = (1.f - z) * n + z * hp;
        S.hnext[(size_t)s * 512 + jc] = hn;
        S.out[(size_t)token * S.outStride + S.outOff + jc] = hn;
    }
}

// ---------------------------------------------------------------------------
// Launch
// ---------------------------------------------------------------------------
extern "C" void kernel_launch(void* const* d_in, const int* in_sizes, int n_in,
                              void* d_out_v, int out_size)
{
    const float* x_time = (const float*)d_in[0];
    const float* x_freq = (const float*)d_in[1];
    const float* wt_ih  = (const float*)d_in[2];
    const float* wt_hh  = (const float*)d_in[3];
    const float* bt_ih  = (const float*)d_in[4];
    const float* bt_hh  = (const float*)d_in[5];
    const float* wf_ih  = (const float*)d_in[6];
    const float* wf_hh  = (const float*)d_in[7];
    const float* bf_ih  = (const float*)d_in[8];
    const float* bf_hh  = (const float*)d_in[9];
    const float* wb_ih  = (const float*)d_in[10];
    const float* wb_hh  = (const float*)d_in[11];
    const float* bb_ih  = (const float*)d_in[12];
    const float* bb_hh  = (const float*)d_in[13];
    const float* ws_ih  = (const float*)d_in[14];
    const float* ws_hh  = (const float*)d_in[15];
    const float* bs_ih  = (const float*)d_in[16];
    const float* bs_hh  = (const float*)d_in[17];
    const float* W_time = (const float*)d_in[18];
    const float* b_time = (const float*)d_in[19];
    const float* W_freq = (const float*)d_in[20];
    const float* b_freq = (const float*)d_in[21];
    float* dout = (float*)d_out_v;

    float *gi_t, *gi_f, *gi_b, *gi_s, *xcat, *xs, *h0, *h1, *h2, *h3;
    cudaGetSymbolAddress((void**)&gi_t, g_gi_t);
    cudaGetSymbolAddress((void**)&gi_f, g_gi_f);
    cudaGetSymbolAddress((void**)&gi_b, g_gi_b);
    cudaGetSymbolAddress((void**)&gi_s, g_gi_s);
    cudaGetSymbolAddress((void**)&xcat, g_xcat);
    cudaGetSymbolAddress((void**)&xs,   g_xs);
    cudaGetSymbolAddress((void**)&h0,   g_h0);
    cudaGetSymbolAddress((void**)&h1,   g_h1);
    cudaGetSymbolAddress((void**)&h2,   g_h2);
    cudaGetSymbolAddress((void**)&h3,   g_h3);

    const dim3 blk(256);

    // ---- Phase 1: input projections for time / freq-fwd / freq-bwd GRUs ----
    {
        dim3 grid(G3 / 64, NT / 128);
        gemm_tn<<<grid, blk>>>(x_time, nullptr, wt_ih, bt_ih, nullptr, gi_t, Dd, G3);
        gemm_tn<<<grid, blk>>>(x_time, nullptr, wf_ih, bf_ih, nullptr, gi_f, Dd, G3);
        gemm_tn<<<grid, blk>>>(x_time, nullptr, wb_ih, bb_ih, nullptr, gi_b, Dd, G3);
    }

    // ---- Phase 2: time GRU scan (256 steps, 160 sequences) ----
    cudaMemsetAsync(h0, 0, (size_t)NSEQ_T * Dd * sizeof(float));
    for (int t = 0; t < Tt; t++) {
        float* hp = (t & 1) ? h1 : h0;
        float* hn = (t & 1) ? h0 : h1;
        GruSet S{hp, hn, gi_t, wt_hh, bt_hh, xcat, G3, 0, 0};
        gru_step<8, true><<<dim3(NSEQ_T / 8, 16, 1), blk>>>(S, S, t);
    }

    // ---- Phase 3: bidirectional freq GRU scan (80 steps, 512 seqs x 2 dirs) --
    cudaMemsetAsync(h0, 0, (size_t)NSEQ_F * Dd * sizeof(float));
    cudaMemsetAsync(h2, 0, (size_t)NSEQ_F * Dd * sizeof(float));
    for (int s = 0; s < Mm; s++) {
        float* hpF = (s & 1) ? h1 : h0;
        float* hnF = (s & 1) ? h0 : h1;
        float* hpB = (s & 1) ? h3 : h2;
        float* hnB = (s & 1) ? h2 : h3;
        GruSet SF{hpF, hnF, gi_f, wf_hh, bf_hh, xcat, G3, Dd,      s};
        GruSet SB{hpB, hnB, gi_b, wb_hh, bb_hh, xcat, G3, 2 * Dd,  Mm - 1 - s};
        gru_step<32, false><<<dim3(NSEQ_F / 32, 16, 2), blk>>>(SF, SB, 0);
    }

    // ---- Phase 4: xt = xcat @ W_time^T + b_time + x_time  -> dout[0:NT*D] ---
    gemm_tn<<<dim3(Dd / 64, NT / 128), blk>>>(
        xcat, nullptr, W_time, b_time, x_time, dout, G3, Dd);

    // ---- Phase 5: gi_s = (xt + x_freq) @ ws_ih^T + bs_ih ----
    gemm_tn<<<dim3(G3 / 64, NT / 128), blk>>>(
        dout, x_freq, ws_ih, bs_ih, nullptr, gi_s, Dd, G3);

    // ---- Phase 6: stack GRU scan (80 steps, 512 sequences) ----
    cudaMemsetAsync(h0, 0, (size_t)NSEQ_F * Dd * sizeof(float));
    for (int s = 0; s < Mm; s++) {
        float* hp = (s & 1) ? h1 : h0;
        float* hn = (s & 1) ? h0 : h1;
        GruSet S{hp, hn, gi_s, ws_hh, bs_hh, xs, Dd, 0, s};
        gru_step<32, false><<<dim3(NSEQ_F / 32, 16, 1), blk>>>(S, S, 0);
    }

    // ---- Phase 7: xf = xs @ W_freq^T + b_freq + x_freq -> dout[NT*D:] ----
    gemm_tn<<<dim3(Dd / 64, NT / 128), blk>>>(
        xs, nullptr, W_freq, b_freq, x_freq, dout + (size_t)NT * Dd, Dd, Dd);
}

// round 3
// speedup vs baseline: 1.2994x; 1.2994x over previous
#include <cuda_runtime.h>
#include <cstdint>

// ---------------------------------------------------------------------------
// Problem constants (fixed shapes from reference)
// ---------------------------------------------------------------------------
constexpr int Bb = 2, Tt = 256, Mm = 80, Dd = 512;
constexpr int NT = Bb * Tt * Mm;   // 40960 tokens
constexpr int G3 = 3 * Dd;         // 1536
constexpr int NSEQ_T = Bb * Mm;    // 160 time-GRU sequences
constexpr int NSEQ_F = Bb * Tt;    // 512 freq-GRU sequences

// persistent time-scan partitioning
constexpr int TGROUPS = 8;         // sequence groups
constexpr int TSQ = NSEQ_T / TGROUPS;  // 20 seqs per group
constexpr int TCOLB = 16;          // column blocks per group (32 h-cols each)

// ---------------------------------------------------------------------------
// Scratch (static device memory; no runtime allocation allowed)
// ---------------------------------------------------------------------------
__device__ float g_gi_t[(size_t)NT * G3];   // time GRU input projections
__device__ float g_gi_f[(size_t)NT * G3];   // freq fwd GRU input projections
__device__ float g_gi_b[(size_t)NT * G3];   // freq bwd GRU input projections
__device__ float g_gi_s[(size_t)NT * G3];   // stack GRU input projections
__device__ float g_xcat[(size_t)NT * G3];   // concat(x1, fwd, bwd)
__device__ float g_xs[(size_t)NT * Dd];     // stack GRU outputs
__device__ float g_h0[NSEQ_F * Dd];         // hidden ping/pong buffers
__device__ float g_h1[NSEQ_F * Dd];
__device__ float g_h2[NSEQ_F * Dd];
__device__ float g_h3[NSEQ_F * Dd];
__device__ unsigned g_tbar[TGROUPS];        // per-group step barrier counters

// ---------------------------------------------------------------------------
// Generic GEMM:  C[Mr,N] = (A (+A2))[Mr,K] @ W[N,K]^T + bias[N] (+ res[Mr,N])
// ---------------------------------------------------------------------------
__global__ __launch_bounds__(256) void gemm_tn(
    const float* __restrict__ A, const float* __restrict__ A2,
    const float* __restrict__ W, const float* __restrict__ bias,
    const float* __restrict__ res, float* __restrict__ C,
    int K, int N)
{
    __shared__ float As[16][132];  // [k][row], padded
    __shared__ float Ws[16][68];   // [k][col], padded

    const int tid = threadIdx.x;
    const int row0 = blockIdx.y * 128;
    const int col0 = blockIdx.x * 64;
    const int tx = tid & 15;
    const int ty = tid >> 4;

    float acc[8][4];
#pragma unroll
    for (int i = 0; i < 8; i++)
#pragma unroll
        for (int j = 0; j < 4; j++) acc[i][j] = 0.f;

    for (int k0 = 0; k0 < K; k0 += 16) {
#pragma unroll
        for (int i = 0; i < 2; i++) {
            int idx = tid * 2 + i;
            int r = idx >> 2;
            int c4 = (idx & 3) * 4;
            float4 v = *reinterpret_cast<const float4*>(
                A + (size_t)(row0 + r) * K + k0 + c4);
            if (A2) {
                float4 w = *reinterpret_cast<const float4*>(
                    A2 + (size_t)(row0 + r) * K + k0 + c4);
                v.x += w.x; v.y += w.y; v.z += w.z; v.w += w.w;
            }
            As[c4 + 0][r] = v.x; As[c4 + 1][r] = v.y;
            As[c4 + 2][r] = v.z; As[c4 + 3][r] = v.w;
        }
        {
            int r = tid >> 2;
            int c4 = (tid & 3) * 4;
            float4 v = *reinterpret_cast<const float4*>(
                W + (size_t)(col0 + r) * K + k0 + c4);
            Ws[c4 + 0][r] = v.x; Ws[c4 + 1][r] = v.y;
            Ws[c4 + 2][r] = v.z; Ws[c4 + 3][r] = v.w;
        }
        __syncthreads();

#pragma unroll
        for (int kk = 0; kk < 16; kk++) {
            float a[8], b[4];
            *reinterpret_cast<float4*>(a) =
                *reinterpret_cast<const float4*>(&As[kk][ty * 8]);
            *reinterpret_cast<float4*>(a + 4) =
                *reinterpret_cast<const float4*>(&As[kk][ty * 8 + 4]);
            *reinterpret_cast<float4*>(b) =
                *reinterpret_cast<const float4*>(&Ws[kk][tx * 4]);
#pragma unroll
            for (int i = 0; i < 8; i++)
#pragma unroll
                for (int j = 0; j < 4; j++)
                    acc[i][j] += a[i] * b[j];
        }
        __syncthreads();
    }

#pragma unroll
    for (int i = 0; i < 8; i++) {
        int r = row0 + ty * 8 + i;
#pragma unroll
        for (int j = 0; j < 4; j++) {
            int c = col0 + tx * 4 + j;
            float v = acc[i][j] + bias[c];
            if (res) v += res[(size_t)r * N + c];
            C[(size_t)r * N + c] = v;
        }
    }
}

// ---------------------------------------------------------------------------
// Activation helpers
// ---------------------------------------------------------------------------
__device__ __forceinline__ float sigf(float x) {
    return 1.f / (1.f + __expf(-x));
}
__device__ __forceinline__ float tanhfast(float x) {
    float e2x = __expf(2.f * x);
    return 1.f - 2.f / (e2x + 1.f);
}

// ---------------------------------------------------------------------------
// Persistent time-GRU scan.
// Grid: (TGROUPS=8, TCOLB=16). Block: 256 threads (8 warps).
// Block (g, cb) owns sequences [g*20, g*20+20) and h-columns [cb*32, cb*32+32),
// all 3 gates. Warp w covers k-slice [w*64, w*64+64); each thread keeps its
// W_hh slice (3 gates x 64 k for column j=lane) in 192 registers for all 256
// steps. h ping-pongs through gmem; 16 col-blocks of a group sync with a
// monotonically increasing atomic counter per step.
// ---------------------------------------------------------------------------
__global__ __launch_bounds__(256, 1) void gru_time_persist(
    const float* __restrict__ gi, const float* __restrict__ Whh,
    const float* __restrict__ bhh, float* __restrict__ out,
    float* __restrict__ hb0, float* __restrict__ hb1)
{
    const int grp  = blockIdx.x;           // 0..7
    const int cb   = blockIdx.y;           // 0..15
    const int j0   = cb * 32;
    const int tid  = threadIdx.x;
    const int lane = tid & 31;
    const int w    = tid >> 5;
    const int k0   = w * 64;

    extern __shared__ float sm[];
    float* hs   = sm;                       // [TSQ][512]  = 40KB
    float* part = sm + TSQ * 512;           // [TSQ][3][32][8] = 61.4KB

    // ---- load W slice into registers (once) ----
    float wr[64], wz[64], wn[64];
    {
        const float* Wr = Whh + (size_t)(0 * Dd + j0 + lane) * Dd + k0;
        const float* Wz = Whh + (size_t)(1 * Dd + j0 + lane) * Dd + k0;
        const float* Wn = Whh + (size_t)(2 * Dd + j0 + lane) * Dd + k0;
#pragma unroll
        for (int i = 0; i < 64; i += 4) {
            float4 a = *reinterpret_cast<const float4*>(Wr + i);
            float4 b = *reinterpret_cast<const float4*>(Wz + i);
            float4 c = *reinterpret_cast<const float4*>(Wn + i);
            wr[i] = a.x; wr[i+1] = a.y; wr[i+2] = a.z; wr[i+3] = a.w;
            wz[i] = b.x; wz[i+1] = b.y; wz[i+2] = b.z; wz[i+3] = b.w;
            wn[i] = c.x; wn[i+1] = c.y; wn[i+2] = c.z; wn[i+3] = c.w;
        }
    }

    for (int t = 0; t < Tt; t++) {
        const float* hc = (t & 1) ? hb1 : hb0;
        float*       hn = (t & 1) ? hb0 : hb1;

        // ---- stage h_prev for this group's 20 seqs into smem ----
        for (int i = tid; i < TSQ * 128; i += 256) {       // 128 float4 per seq
            int s  = i >> 7;
            int k4 = i & 127;
            float4 v = __ldcg(reinterpret_cast<const float4*>(
                hc + (size_t)(grp * TSQ + s) * Dd) + k4);
            *reinterpret_cast<float4*>(hs + s * Dd + k4 * 4) = v;
        }
        __syncthreads();

        // ---- partial matvecs: warp w covers k in [k0, k0+64) ----
        for (int s = 0; s < TSQ; s++) {
            float ar = 0.f, az = 0.f, an = 0.f;
            const float* hrow = hs + s * Dd + k0;
#pragma unroll
            for (int i = 0; i < 64; i += 4) {
                float4 h4 = *reinterpret_cast<const float4*>(hrow + i);
                ar = fmaf(h4.x, wr[i],   ar); az = fmaf(h4.x, wz[i],   az); an = fmaf(h4.x, wn[i],   an);
                ar = fmaf(h4.y, wr[i+1], ar); az = fmaf(h4.y, wz[i+1], az); an = fmaf(h4.y, wn[i+1], an);
                ar = fmaf(h4.z, wr[i+2], ar); az = fmaf(h4.z, wz[i+2], az); an = fmaf(h4.z, wn[i+2], an);
                ar = fmaf(h4.w, wr[i+3], ar); az = fmaf(h4.w, wz[i+3], az); an = fmaf(h4.w, wn[i+3], an);
            }
            part[((s * 3 + 0) * 32 + lane) * 8 + w] = ar;
            part[((s * 3 + 1) * 32 + lane) * 8 + w] = az;
            part[((s * 3 + 2) * 32 + lane) * 8 + w] = an;
        }
        __syncthreads();

        // ---- reduce partials, apply gates, update h, write output ----
        for (int idx = tid; idx < TSQ * 32; idx += 256) {
            int s = idx >> 5, j = idx & 31;
            float r = 0.f, z = 0.f, n = 0.f;
            const float* pr = part + ((s * 3 + 0) * 32 + j) * 8;
            const float* pz = part + ((s * 3 + 1) * 32 + j) * 8;
            const float* pn = part + ((s * 3 + 2) * 32 + j) * 8;
#pragma unroll
            for (int ww = 0; ww < 8; ww++) { r += pr[ww]; z += pz[ww]; n += pn[ww]; }

            int sg = grp * TSQ + s;
            int b  = sg / Mm;
            int m  = sg - b * Mm;
            size_t token = ((size_t)(b * Tt + t)) * Mm + m;
            const float* gir = gi + token * G3;
            int jc = j0 + j;
            float rr = sigf(gir[jc]        + r + bhh[jc]);
            float zz = sigf(gir[Dd + jc]   + z + bhh[Dd + jc]);
            float nn = tanhfast(gir[2*Dd + jc] + rr * (n + bhh[2*Dd + jc]));
            float hp = hs[s * Dd + jc];
            float hv = (1.f - zz) * nn + zz * hp;
            __stcg(hn + (size_t)sg * Dd + jc, hv);
            out[token * G3 + jc] = hv;     // xcat, column block [0, 512)
        }

        // ---- inter-block barrier for this sequence group ----
        __threadfence();
        __syncthreads();
        if (tid == 0) {
            atomicAdd(&g_tbar[grp], 1u);
            unsigned target = (unsigned)(t + 1) * TCOLB;
            while (atomicAdd(&g_tbar[grp], 0u) < target) {
                __nanosleep(64);
            }
        }
        __syncthreads();
    }
}

// ---------------------------------------------------------------------------
// Per-step GRU kernel (kept for freq-bi and stack scans)
// ---------------------------------------------------------------------------
struct GruSet {
    const float* hprev;
    float*       hnext;
    const float* gi;
    const float* Whh;
    const float* bhh;
    float*       out;
    int outStride;
    int outOff;
    int mtok;
};

template <int TS>
__global__ __launch_bounds__(256) void gru_step(GruSet S0, GruSet S1, int t)
{
    const GruSet S = (blockIdx.z == 0) ? S0 : S1;
    constexpr int SPW = TS / 8;

    __shared__ float Hs[TS][33];
    __shared__ float Ws[3][32][33];

    const int tid = threadIdx.x;
    const int lane = tid & 31;
    const int warp = tid >> 5;
    const int s0 = blockIdx.x * TS;
    const int j0 = blockIdx.y * 32;

    float accR[SPW], accZ[SPW], accN[SPW];
#pragma unroll
    for (int u = 0; u < SPW; u++) { accR[u] = 0.f; accZ[u] = 0.f; accN[u] = 0.f; }

    for (int k0 = 0; k0 < 512; k0 += 32) {
        if (tid < TS * 8) {
            int ss = tid >> 3;
            int c4 = (tid & 7) * 4;
            float4 v = *reinterpret_cast<const float4*>(
                S.hprev + (size_t)(s0 + ss) * 512 + k0 + c4);
            Hs[ss][c4 + 0] = v.x; Hs[ss][c4 + 1] = v.y;
            Hs[ss][c4 + 2] = v.z; Hs[ss][c4 + 3] = v.w;
        }
        {
            int jj = tid >> 3;
            int c4 = (tid & 7) * 4;
#pragma unroll
            for (int g = 0; g < 3; g++) {
                float4 v = *reinterpret_cast<const float4*>(
                    S.Whh + (size_t)(g * 512 + j0 + jj) * 512 + k0 + c4);
                Ws[g][jj][c4 + 0] = v.x; Ws[g][jj][c4 + 1] = v.y;
                Ws[g][jj][c4 + 2] = v.z; Ws[g][jj][c4 + 3] = v.w;
            }
        }
        __syncthreads();

#pragma unroll
        for (int kk = 0; kk < 32; kk++) {
            float wrv = Ws[0][lane][kk];
            float wzv = Ws[1][lane][kk];
            float wnv = Ws[2][lane][kk];
#pragma unroll
            for (int u = 0; u < SPW; u++) {
                float hv = Hs[warp * SPW + u][kk];
                accR[u] += hv * wrv;
                accZ[u] += hv * wzv;
                accN[u] += hv * wnv;
            }
        }
        __syncthreads();
    }

    const int jc = j0 + lane;
    const float br = S.bhh[jc];
    const float bz = S.bhh[512 + jc];
    const float bn = S.bhh[1024 + jc];

#pragma unroll
    for (int u = 0; u < SPW; u++) {
        int s = s0 + warp * SPW + u;
        int token = s * Mm + S.mtok;
        const float* gir = S.gi + (size_t)token * G3;
        float r = sigf(gir[jc] + accR[u] + br);
        float z = sigf(gir[512 + jc] + accZ[u] + bz);
        float n = tanhfast(gir[1024 + jc] + r * (accN[u] + bn));
        float hp = S.hprev[(size_t)s * 512 + jc];
        float hn = (1.f - z) * n + z * hp;
        S.hnext[(size_t)s * 512 + jc] = hn;
        S.out[(size_t)token * S.outStride + S.outOff + jc] = hn;
    }
}

// ---------------------------------------------------------------------------
// Launch
// ---------------------------------------------------------------------------
extern "C" void kernel_launch(void* const* d_in, const int* in_sizes, int n_in,
                              void* d_out_v, int out_size)
{
    const float* x_time = (const float*)d_in[0];
    const float* x_freq = (const float*)d_in[1];
    const float* wt_ih  = (const float*)d_in[2];
    const float* wt_hh  = (const float*)d_in[3];
    const float* bt_ih  = (const float*)d_in[4];
    const float* bt_hh  = (const float*)d_in[5];
    const float* wf_ih  = (const float*)d_in[6];
    const float* wf_hh  = (const float*)d_in[7];
    const float* bf_ih  = (const float*)d_in[8];
    const float* bf_hh  = (const float*)d_in[9];
    const float* wb_ih  = (const float*)d_in[10];
    const float* wb_hh  = (const float*)d_in[11];
    const float* bb_ih  = (const float*)d_in[12];
    const float* bb_hh  = (const float*)d_in[13];
    const float* ws_ih  = (const float*)d_in[14];
    const float* ws_hh  = (const float*)d_in[15];
    const float* bs_ih  = (const float*)d_in[16];
    const float* bs_hh  = (const float*)d_in[17];
    const float* W_time = (const float*)d_in[18];
    const float* b_time = (const float*)d_in[19];
    const float* W_freq = (const float*)d_in[20];
    const float* b_freq = (const float*)d_in[21];
    float* dout = (float*)d_out_v;

    float *gi_t, *gi_f, *gi_b, *gi_s, *xcat, *xs, *h0, *h1, *h2, *h3;
    unsigned* tbar;
    cudaGetSymbolAddress((void**)&gi_t, g_gi_t);
    cudaGetSymbolAddress((void**)&gi_f, g_gi_f);
    cudaGetSymbolAddress((void**)&gi_b, g_gi_b);
    cudaGetSymbolAddress((void**)&gi_s, g_gi_s);
    cudaGetSymbolAddress((void**)&xcat, g_xcat);
    cudaGetSymbolAddress((void**)&xs,   g_xs);
    cudaGetSymbolAddress((void**)&h0,   g_h0);
    cudaGetSymbolAddress((void**)&h1,   g_h1);
    cudaGetSymbolAddress((void**)&h2,   g_h2);
    cudaGetSymbolAddress((void**)&h3,   g_h3);
    cudaGetSymbolAddress((void**)&tbar, g_tbar);

    const dim3 blk(256);
    const int persist_smem = (TSQ * 512 + TSQ * 3 * 32 * 8) * sizeof(float); // 102400
    cudaFuncSetAttribute(gru_time_persist,
                         cudaFuncAttributeMaxDynamicSharedMemorySize, persist_smem);

    // ---- Phase 1: input projections for time / freq-fwd / freq-bwd GRUs ----
    {
        dim3 grid(G3 / 64, NT / 128);
        gemm_tn<<<grid, blk>>>(x_time, nullptr, wt_ih, bt_ih, nullptr, gi_t, Dd, G3);
        gemm_tn<<<grid, blk>>>(x_time, nullptr, wf_ih, bf_ih, nullptr, gi_f, Dd, G3);
        gemm_tn<<<grid, blk>>>(x_time, nullptr, wb_ih, bb_ih, nullptr, gi_b, Dd, G3);
    }

    // ---- Phase 2: persistent time GRU scan (256 steps, 160 sequences) ----
    cudaMemsetAsync(h0, 0, (size_t)NSEQ_T * Dd * sizeof(float));
    cudaMemsetAsync(h1, 0, (size_t)NSEQ_T * Dd * sizeof(float));
    cudaMemsetAsync(tbar, 0, TGROUPS * sizeof(unsigned));
    gru_time_persist<<<dim3(TGROUPS, TCOLB), blk, persist_smem>>>(
        gi_t, wt_hh, bt_hh, xcat, h0, h1);

    // ---- Phase 3: bidirectional freq GRU scan (80 steps, 512 seqs x 2 dirs) --
    cudaMemsetAsync(h0, 0, (size_t)NSEQ_F * Dd * sizeof(float));
    cudaMemsetAsync(h2, 0, (size_t)NSEQ_F * Dd * sizeof(float));
    for (int s = 0; s < Mm; s++) {
        float* hpF = (s & 1) ? h1 : h0;
        float* hnF = (s & 1) ? h0 : h1;
        float* hpB = (s & 1) ? h3 : h2;
        float* hnB = (s & 1) ? h2 : h3;
        GruSet SF{hpF, hnF, gi_f, wf_hh, bf_hh, xcat, G3, Dd,      s};
        GruSet SB{hpB, hnB, gi_b, wb_hh, bb_hh, xcat, G3, 2 * Dd,  Mm - 1 - s};
        gru_step<32><<<dim3(NSEQ_F / 32, 16, 2), blk>>>(SF, SB, 0);
    }

    // ---- Phase 4: xt = xcat @ W_time^T + b_time + x_time  -> dout[0:NT*D] ---
    gemm_tn<<<dim3(Dd / 64, NT / 128), blk>>>(
        xcat, nullptr, W_time, b_time, x_time, dout, G3, Dd);

    // ---- Phase 5: gi_s = (xt + x_freq) @ ws_ih^T + bs_ih ----
    gemm_tn<<<dim3(G3 / 64, NT / 128), blk>>>(
        dout, x_freq, ws_ih, bs_ih, nullptr, gi_s, Dd, G3);

    // ---- Phase 6: stack GRU scan (80 steps, 512 sequences) ----
    cudaMemsetAsync(h0, 0, (size_t)NSEQ_F * Dd * sizeof(float));
    for (int s = 0; s < Mm; s++) {
        float* hp = (s & 1) ? h1 : h0;
        float* hn = (s & 1) ? h0 : h1;
        GruSet S{hp, hn, gi_s, ws_hh, bs_hh, xs, Dd, 0, s};
        gru_step<32><<<dim3(NSEQ_F / 32, 16, 1), blk>>>(S, S, 0);
    }

    // ---- Phase 7: xf = xs @ W_freq^T + b_freq + x_freq -> dout[NT*D:] ----
    gemm_tn<<<dim3(Dd / 64, NT / 128), blk>>>(
        xs, nullptr, W_freq, b_freq, x_freq, dout + (size_t)NT * Dd, Dd, Dd);
}

// round 5
// speedup vs baseline: 1.7227x; 1.3257x over previous
#include <cuda_runtime.h>
#include <cuda_bf16.h>
#include <cstdint>

// ---------------------------------------------------------------------------
// Problem constants
// ---------------------------------------------------------------------------
constexpr int Bb = 2, Tt = 256, Mm = 80, Dd = 512;
constexpr int NT = Bb * Tt * Mm;   // 40960 tokens
constexpr int G3 = 3 * Dd;         // 1536
constexpr int NSEQ_T = Bb * Mm;    // 160
constexpr int NSEQ_F = Bb * Tt;    // 512

constexpr int TGROUPS = 8;
constexpr int TSQ = NSEQ_T / TGROUPS;  // 20
constexpr int TCOLB = 16;

// ---------------------------------------------------------------------------
// Static device scratch
// ---------------------------------------------------------------------------
__device__ float g_gi_t[(size_t)NT * G3];
__device__ float g_gi_f[(size_t)NT * G3];
__device__ float g_gi_b[(size_t)NT * G3];
__device__ float g_gi_s[(size_t)NT * G3];
__device__ float g_xcat[(size_t)NT * G3];
__device__ float g_xs[(size_t)NT * Dd];
__device__ float g_h0[NSEQ_F * Dd];
__device__ float g_h1[NSEQ_F * Dd];
__device__ float g_h2[NSEQ_F * Dd];
__device__ float g_h3[NSEQ_F * Dd];
__device__ unsigned g_tbar[TGROUPS];

// bf16 split buffers
__device__ __nv_bfloat16 g_ahi[(size_t)NT * G3];
__device__ __nv_bfloat16 g_alo[(size_t)NT * G3];
constexpr size_t WSLOT = 786432;  // 1536*512
__device__ __nv_bfloat16 g_whi[6 * WSLOT];
__device__ __nv_bfloat16 g_wlo[6 * WSLOT];

// ---------------------------------------------------------------------------
// PTX helpers (portable: cp.async / ldmatrix / mma.sync — no 'a' features)
// ---------------------------------------------------------------------------
__device__ __forceinline__ uint32_t smem_to_u32(const void* p) {
    uint32_t a;
    asm("{ .reg .u64 t; cvta.to.shared.u64 t, %1; cvt.u32.u64 %0, t; }"
        : "=r"(a) : "l"(p));
    return a;
}
#define CP_ASYNC16(dst, src) \
    asm volatile("cp.async.cg.shared.global [%0], [%1], 16;" \
        :: "r"((uint32_t)(dst)), "l"(src) : "memory")
#define CP_COMMIT() asm volatile("cp.async.commit_group;" ::: "memory")
#define CP_WAIT(n)  asm volatile("cp.async.wait_group %0;" :: "n"(n) : "memory")

__device__ __forceinline__ void ldsm4(uint32_t* r, uint32_t addr) {
    asm volatile("ldmatrix.sync.aligned.m8n8.x4.shared.b16 {%0,%1,%2,%3}, [%4];"
        : "=r"(r[0]), "=r"(r[1]), "=r"(r[2]), "=r"(r[3]) : "r"(addr));
}
__device__ __forceinline__ void mma16816(float* c, const uint32_t* a, const uint32_t* b) {
    asm volatile(
        "mma.sync.aligned.m16n8k16.row.col.f32.bf16.bf16.f32 "
        "{%0,%1,%2,%3}, {%4,%5,%6,%7}, {%8,%9}, {%0,%1,%2,%3};"
        : "+f"(c[0]), "+f"(c[1]), "+f"(c[2]), "+f"(c[3])
        : "r"(a[0]), "r"(a[1]), "r"(a[2]), "r"(a[3]), "r"(b[0]), "r"(b[1]));
}

// ---------------------------------------------------------------------------
// fp32 -> (hi,lo) bf16 split (optionally X+Y first)
// ---------------------------------------------------------------------------
__global__ void split_bf16_kernel(
    const float* __restrict__ X, const float* __restrict__ Y,
    __nv_bfloat16* __restrict__ hi, __nv_bfloat16* __restrict__ lo, int n4)
{
    int i = blockIdx.x * blockDim.x + threadIdx.x;
    if (i >= n4) return;
    float4 v = reinterpret_cast<const float4*>(X)[i];
    if (Y) {
        float4 y = reinterpret_cast<const float4*>(Y)[i];
        v.x += y.x; v.y += y.y; v.z += y.z; v.w += y.w;
    }
    __nv_bfloat16 h0 = __float2bfloat16_rn(v.x);
    __nv_bfloat16 h1 = __float2bfloat16_rn(v.y);
    __nv_bfloat16 h2 = __float2bfloat16_rn(v.z);
    __nv_bfloat16 h3 = __float2bfloat16_rn(v.w);
    __nv_bfloat16 l0 = __float2bfloat16_rn(v.x - __bfloat162float(h0));
    __nv_bfloat16 l1 = __float2bfloat16_rn(v.y - __bfloat162float(h1));
    __nv_bfloat16 l2 = __float2bfloat16_rn(v.z - __bfloat162float(h2));
    __nv_bfloat16 l3 = __float2bfloat16_rn(v.w - __bfloat162float(h3));
    reinterpret_cast<__nv_bfloat162*>(hi)[2*i]   = __nv_bfloat162(h0, h1);
    reinterpret_cast<__nv_bfloat162*>(hi)[2*i+1] = __nv_bfloat162(h2, h3);
    reinterpret_cast<__nv_bfloat162*>(lo)[2*i]   = __nv_bfloat162(l0, l1);
    reinterpret_cast<__nv_bfloat162*>(lo)[2*i+1] = __nv_bfloat162(l2, l3);
}

// ---------------------------------------------------------------------------
// mma.sync GEMM: C[.,N] = A[.,K] @ W[N,K]^T  (3-product bf16 split)
//   + bias[N] (+ res). Block tile 128x128, BK=32, double-buffered cp.async.
// 8 warps: wm = wid&3 (32 rows each), wn = wid>>2 (64 cols each).
// Smem row stride 40 bf16 (80B) -> ldmatrix bank-conflict-free.
// ---------------------------------------------------------------------------
constexpr int GSTRIDE = 40;                    // bf16 elements per smem row
constexpr int TILE_B  = 128 * GSTRIDE * 2;     // 10240 B per operand tile
constexpr int STAGE_B = 4 * TILE_B;            // 40960 B per stage
constexpr int GEMM_SMEM = 2 * STAGE_B;         // 81920 B

__global__ __launch_bounds__(256, 1) void gemm_bf3(
    const __nv_bfloat16* __restrict__ Ahi, const __nv_bfloat16* __restrict__ Alo,
    const __nv_bfloat16* __restrict__ Bhi, const __nv_bfloat16* __restrict__ Blo,
    const float* __restrict__ bias, const float* __restrict__ res,
    float* __restrict__ C, int K, int N)
{
    extern __shared__ char smem[];
    const uint32_t sb = smem_to_u32(smem);
    const int tid  = threadIdx.x;
    const int lane = tid & 31;
    const int wid  = tid >> 5;
    const int wm   = wid & 3;      // 0..3  (32 rows)
    const int wn   = wid >> 2;     // 0..1  (64 cols)
    const int row0 = blockIdx.y * 128;
    const int col0 = blockIdx.x * 128;

    const __nv_bfloat16* srcs[4] = {Ahi, Alo, Bhi, Blo};

    auto stage_load = [&](int c, int buf) {
        const int k0 = c * 32;
        const uint32_t base = sb + buf * STAGE_B;
#pragma unroll
        for (int t4 = 0; t4 < 4; t4++) {
            const __nv_bfloat16* src = srcs[t4];
            const int rbase = (t4 < 2) ? row0 : col0;
#pragma unroll
            for (int i = 0; i < 2; i++) {
                int idx = tid + i * 256;          // 0..511
                int r = idx >> 2;
                int seg = idx & 3;                // 16B segment
                uint32_t dst = base + t4 * TILE_B + r * (GSTRIDE * 2) + seg * 16;
                const void* g = src + (size_t)(rbase + r) * K + k0 + seg * 8;
                CP_ASYNC16(dst, g);
            }
        }
        CP_COMMIT();
    };

    float acc[2][8][4];
#pragma unroll
    for (int mf = 0; mf < 2; mf++)
#pragma unroll
        for (int nf = 0; nf < 8; nf++)
#pragma unroll
            for (int q = 0; q < 4; q++) acc[mf][nf][q] = 0.f;

    const int NC = K / 32;
    stage_load(0, 0);

    for (int c = 0; c < NC; c++) {
        const int buf = c & 1;
        if (c + 1 < NC) {
            stage_load(c + 1, buf ^ 1);
            CP_WAIT(1);
        } else {
            CP_WAIT(0);
        }
        __syncthreads();

        const uint32_t st = sb + buf * STAGE_B;
        // per-lane ldmatrix base offsets
        const uint32_t a_off =
            ((wm * 32 + (lane & 15)) * GSTRIDE + ((lane >> 4) * 8)) * 2;
        const uint32_t b_row = wn * 64 + (lane & 7) + ((lane >> 4) & 1) * 8;
        const uint32_t b_off = (b_row * GSTRIDE + (((lane >> 3) & 1) * 8)) * 2;

#pragma unroll
        for (int kk = 0; kk < 2; kk++) {
            const uint32_t kb = kk * 32;   // 16 bf16 = 32 bytes
            uint32_t ahi[2][4], alo[2][4];
#pragma unroll
            for (int mf = 0; mf < 2; mf++) {
                ldsm4(ahi[mf], st + 0 * TILE_B + a_off + mf * 16 * (GSTRIDE * 2) + kb);
                ldsm4(alo[mf], st + 1 * TILE_B + a_off + mf * 16 * (GSTRIDE * 2) + kb);
            }
            uint32_t bhi[8][2], blo[8][2];
#pragma unroll
            for (int p = 0; p < 4; p++) {
                uint32_t r4[4];
                ldsm4(r4, st + 2 * TILE_B + b_off + p * 16 * (GSTRIDE * 2) + kb);
                bhi[2*p][0] = r4[0]; bhi[2*p][1] = r4[1];
                bhi[2*p+1][0] = r4[2]; bhi[2*p+1][1] = r4[3];
                ldsm4(r4, st + 3 * TILE_B + b_off + p * 16 * (GSTRIDE * 2) + kb);
                blo[2*p][0] = r4[0]; blo[2*p][1] = r4[1];
                blo[2*p+1][0] = r4[2]; blo[2*p+1][1] = r4[3];
            }
#pragma unroll
            for (int mf = 0; mf < 2; mf++)
#pragma unroll
                for (int nf = 0; nf < 8; nf++) {
                    mma16816(acc[mf][nf], ahi[mf], bhi[nf]);
                    mma16816(acc[mf][nf], alo[mf], bhi[nf]);
                    mma16816(acc[mf][nf], ahi[mf], blo[nf]);
                }
        }
        __syncthreads();
    }

    // ---- epilogue ----
#pragma unroll
    for (int mf = 0; mf < 2; mf++) {
        const int rA = row0 + wm * 32 + mf * 16 + (lane >> 2);
        const int rB = rA + 8;
#pragma unroll
        for (int nf = 0; nf < 8; nf++) {
            const int cc = col0 + wn * 64 + nf * 8 + (lane & 3) * 2;
            float2 v0, v1;
            v0.x = acc[mf][nf][0] + bias[cc];
            v0.y = acc[mf][nf][1] + bias[cc + 1];
            v1.x = acc[mf][nf][2] + bias[cc];
            v1.y = acc[mf][nf][3] + bias[cc + 1];
            if (res) {
                float2 r0 = *reinterpret_cast<const float2*>(res + (size_t)rA * N + cc);
                float2 r1 = *reinterpret_cast<const float2*>(res + (size_t)rB * N + cc);
                v0.x += r0.x; v0.y += r0.y; v1.x += r1.x; v1.y += r1.y;
            }
            *reinterpret_cast<float2*>(C + (size_t)rA * N + cc) = v0;
            *reinterpret_cast<float2*>(C + (size_t)rB * N + cc) = v1;
        }
    }
}

// ---------------------------------------------------------------------------
// Activation helpers
// ---------------------------------------------------------------------------
__device__ __forceinline__ float sigf(float x) {
    return 1.f / (1.f + __expf(-x));
}
__device__ __forceinline__ float tanhfast(float x) {
    float e2x = __expf(2.f * x);
    return 1.f - 2.f / (e2x + 1.f);
}

// ---------------------------------------------------------------------------
// Persistent time-GRU scan (unchanged)
// ---------------------------------------------------------------------------
__global__ __launch_bounds__(256, 1) void gru_time_persist(
    const float* __restrict__ gi, const float* __restrict__ Whh,
    const float* __restrict__ bhh, float* __restrict__ out,
    float* __restrict__ hb0, float* __restrict__ hb1)
{
    const int grp  = blockIdx.x;
    const int cb   = blockIdx.y;
    const int j0   = cb * 32;
    const int tid  = threadIdx.x;
    const int lane = tid & 31;
    const int w    = tid >> 5;
    const int k0   = w * 64;

    extern __shared__ float sm[];
    float* hs   = sm;
    float* part = sm + TSQ * 512;

    float wr[64], wz[64], wn[64];
    {
        const float* Wr = Whh + (size_t)(0 * Dd + j0 + lane) * Dd + k0;
        const float* Wz = Whh + (size_t)(1 * Dd + j0 + lane) * Dd + k0;
        const float* Wn = Whh + (size_t)(2 * Dd + j0 + lane) * Dd + k0;
#pragma unroll
        for (int i = 0; i < 64; i += 4) {
            float4 a = *reinterpret_cast<const float4*>(Wr + i);
            float4 b = *reinterpret_cast<const float4*>(Wz + i);
            float4 c = *reinterpret_cast<const float4*>(Wn + i);
            wr[i] = a.x; wr[i+1] = a.y; wr[i+2] = a.z; wr[i+3] = a.w;
            wz[i] = b.x; wz[i+1] = b.y; wz[i+2] = b.z; wz[i+3] = b.w;
            wn[i] = c.x; wn[i+1] = c.y; wn[i+2] = c.z; wn[i+3] = c.w;
        }
    }

    for (int t = 0; t < Tt; t++) {
        const float* hc = (t & 1) ? hb1 : hb0;
        float*       hn = (t & 1) ? hb0 : hb1;

        for (int i = tid; i < TSQ * 128; i += 256) {
            int s  = i >> 7;
            int k4 = i & 127;
            float4 v = __ldcg(reinterpret_cast<const float4*>(
                hc + (size_t)(grp * TSQ + s) * Dd) + k4);
            *reinterpret_cast<float4*>(hs + s * Dd + k4 * 4) = v;
        }
        __syncthreads();

        for (int s = 0; s < TSQ; s++) {
            float ar = 0.f, az = 0.f, an = 0.f;
            const float* hrow = hs + s * Dd + k0;
#pragma unroll
            for (int i = 0; i < 64; i += 4) {
                float4 h4 = *reinterpret_cast<const float4*>(hrow + i);
                ar = fmaf(h4.x, wr[i],   ar); az = fmaf(h4.x, wz[i],   az); an = fmaf(h4.x, wn[i],   an);
                ar = fmaf(h4.y, wr[i+1], ar); az = fmaf(h4.y, wz[i+1], az); an = fmaf(h4.y, wn[i+1], an);
                ar = fmaf(h4.z, wr[i+2], ar); az = fmaf(h4.z, wz[i+2], az); an = fmaf(h4.z, wn[i+2], an);
                ar = fmaf(h4.w, wr[i+3], ar); az = fmaf(h4.w, wz[i+3], az); an = fmaf(h4.w, wn[i+3], an);
            }
            part[((s * 3 + 0) * 32 + lane) * 8 + w] = ar;
            part[((s * 3 + 1) * 32 + lane) * 8 + w] = az;
            part[((s * 3 + 2) * 32 + lane) * 8 + w] = an;
        }
        __syncthreads();

        for (int idx = tid; idx < TSQ * 32; idx += 256) {
            int s = idx >> 5, j = idx & 31;
            float r = 0.f, z = 0.f, n = 0.f;
            const float* pr = part + ((s * 3 + 0) * 32 + j) * 8;
            const float* pz = part + ((s * 3 + 1) * 32 + j) * 8;
            const float* pn = part + ((s * 3 + 2) * 32 + j) * 8;
#pragma unroll
            for (int ww = 0; ww < 8; ww++) { r += pr[ww]; z += pz[ww]; n += pn[ww]; }

            int sg = grp * TSQ + s;
            int b  = sg / Mm;
            int m  = sg - b * Mm;
            size_t token = ((size_t)(b * Tt + t)) * Mm + m;
            const float* gir = gi + token * G3;
            int jc = j0 + j;
            float rr = sigf(gir[jc]        + r + bhh[jc]);
            float zz = sigf(gir[Dd + jc]   + z + bhh[Dd + jc]);
            float nn = tanhfast(gir[2*Dd + jc] + rr * (n + bhh[2*Dd + jc]));
            float hp = hs[s * Dd + jc];
            float hv = (1.f - zz) * nn + zz * hp;
            __stcg(hn + (size_t)sg * Dd + jc, hv);
            out[token * G3 + jc] = hv;
        }

        __threadfence();
        __syncthreads();
        if (tid == 0) {
            atomicAdd(&g_tbar[grp], 1u);
            unsigned target = (unsigned)(t + 1) * TCOLB;
            while (atomicAdd(&g_tbar[grp], 0u) < target) {
                __nanosleep(64);
            }
        }
        __syncthreads();
    }
}

// ---------------------------------------------------------------------------
// Per-step GRU kernel (freq-bi + stack scans)
// ---------------------------------------------------------------------------
struct GruSet {
    const float* hprev;
    float*       hnext;
    const float* gi;
    const float* Whh;
    const float* bhh;
    float*       out;
    int outStride;
    int outOff;
    int mtok;
};

template <int TS>
__global__ __launch_bounds__(256) void gru_step(GruSet S0, GruSet S1, int t)
{
    const GruSet S = (blockIdx.z == 0) ? S0 : S1;
    constexpr int SPW = TS / 8;

    __shared__ float Hs[TS][33];
    __shared__ float Ws[3][32][33];

    const int tid = threadIdx.x;
    const int lane = tid & 31;
    const int warp = tid >> 5;
    const int s0 = blockIdx.x * TS;
    const int j0 = blockIdx.y * 32;

    float accR[SPW], accZ[SPW], accN[SPW];
#pragma unroll
    for (int u = 0; u < SPW; u++) { accR[u] = 0.f; accZ[u] = 0.f; accN[u] = 0.f; }

    for (int k0 = 0; k0 < 512; k0 += 32) {
        if (tid < TS * 8) {
            int ss = tid >> 3;
            int c4 = (tid & 7) * 4;
            float4 v = *reinterpret_cast<const float4*>(
                S.hprev + (size_t)(s0 + ss) * 512 + k0 + c4);
            Hs[ss][c4 + 0] = v.x; Hs[ss][c4 + 1] = v.y;
            Hs[ss][c4 + 2] = v.z; Hs[ss][c4 + 3] = v.w;
        }
        {
            int jj = tid >> 3;
            int c4 = (tid & 7) * 4;
#pragma unroll
            for (int g = 0; g < 3; g++) {
                float4 v = *reinterpret_cast<const float4*>(
                    S.Whh + (size_t)(g * 512 + j0 + jj) * 512 + k0 + c4);
                Ws[g][jj][c4 + 0] = v.x; Ws[g][jj][c4 + 1] = v.y;
                Ws[g][jj][c4 + 2] = v.z; Ws[g][jj][c4 + 3] = v.w;
            }
        }
        __syncthreads();

#pragma unroll
        for (int kk = 0; kk < 32; kk++) {
            float wrv = Ws[0][lane][kk];
            float wzv = Ws[1][lane][kk];
            float wnv = Ws[2][lane][kk];
#pragma unroll
            for (int u = 0; u < SPW; u++) {
                float hv = Hs[warp * SPW + u][kk];
                accR[u] += hv * wrv;
                accZ[u] += hv * wzv;
                accN[u] += hv * wnv;
            }
        }
        __syncthreads();
    }

    const int jc = j0 + lane;
    const float br = S.bhh[jc];
    const float bz = S.bhh[512 + jc];
    const float bn = S.bhh[1024 + jc];

#pragma unroll
    for (int u = 0; u < SPW; u++) {
        int s = s0 + warp * SPW + u;
        int token = s * Mm + S.mtok;
        const float* gir = S.gi + (size_t)token * G3;
        float r = sigf(gir[jc] + accR[u] + br);
        float z = sigf(gir[512 + jc] + accZ[u] + bz);
        float n = tanhfast(gir[1024 + jc] + r * (accN[u] + bn));
        float hp = S.hprev[(size_t)s * 512 + jc];
        float hn = (1.f - z) * n + z * hp;
        S.hnext[(size_t)s * 512 + jc] = hn;
        S.out[(size_t)token * S.outStride + S.outOff + jc] = hn;
    }
}

// ---------------------------------------------------------------------------
// Launch
// ---------------------------------------------------------------------------
static void split_launch(const float* X, const float* Y,
                         __nv_bfloat16* hi, __nv_bfloat16* lo, size_t n)
{
    int n4 = (int)(n / 4);
    split_bf16_kernel<<<(n4 + 255) / 256, 256>>>(X, Y, hi, lo, n4);
}

extern "C" void kernel_launch(void* const* d_in, const int* in_sizes, int n_in,
                              void* d_out_v, int out_size)
{
    const float* x_time = (const float*)d_in[0];
    const float* x_freq = (const float*)d_in[1];
    const float* wt_ih  = (const float*)d_in[2];
    const float* wt_hh  = (const float*)d_in[3];
    const float* bt_ih  = (const float*)d_in[4];
    const float* bt_hh  = (const float*)d_in[5];
    const float* wf_ih  = (const float*)d_in[6];
    const float* wf_hh  = (const float*)d_in[7];
    const float* bf_ih  = (const float*)d_in[8];
    const float* bf_hh  = (const float*)d_in[9];
    const float* wb_ih  = (const float*)d_in[10];
    const float* wb_hh  = (const float*)d_in[11];
    const float* bb_ih  = (const float*)d_in[12];
    const float* bb_hh  = (const float*)d_in[13];
    const float* ws_ih  = (const float*)d_in[14];
    const float* ws_hh  = (const float*)d_in[15];
    const float* bs_ih  = (const float*)d_in[16];
    const float* bs_hh  = (const float*)d_in[17];
    const float* W_time = (const float*)d_in[18];
    const float* b_time = (const float*)d_in[19];
    const float* W_freq = (const float*)d_in[20];
    const float* b_freq = (const float*)d_in[21];
    float* dout = (float*)d_out_v;

    float *gi_t, *gi_f, *gi_b, *gi_s, *xcat, *xs, *h0, *h1, *h2, *h3;
    unsigned* tbar;
    __nv_bfloat16 *ahi, *alo, *whi, *wlo;
    cudaGetSymbolAddress((void**)&gi_t, g_gi_t);
    cudaGetSymbolAddress((void**)&gi_f, g_gi_f);
    cudaGetSymbolAddress((void**)&gi_b, g_gi_b);
    cudaGetSymbolAddress((void**)&gi_s, g_gi_s);
    cudaGetSymbolAddress((void**)&xcat, g_xcat);
    cudaGetSymbolAddress((void**)&xs,   g_xs);
    cudaGetSymbolAddress((void**)&h0,   g_h0);
    cudaGetSymbolAddress((void**)&h1,   g_h1);
    cudaGetSymbolAddress((void**)&h2,   g_h2);
    cudaGetSymbolAddress((void**)&h3,   g_h3);
    cudaGetSymbolAddress((void**)&tbar, g_tbar);
    cudaGetSymbolAddress((void**)&ahi,  g_ahi);
    cudaGetSymbolAddress((void**)&alo,  g_alo);
    cudaGetSymbolAddress((void**)&whi,  g_whi);
    cudaGetSymbolAddress((void**)&wlo,  g_wlo);

    const dim3 blk(256);
    const int persist_smem = (TSQ * 512 + TSQ * 3 * 32 * 8) * sizeof(float);
    cudaFuncSetAttribute(gru_time_persist,
                         cudaFuncAttributeMaxDynamicSharedMemorySize, persist_smem);
    cudaFuncSetAttribute(gemm_bf3,
                         cudaFuncAttributeMaxDynamicSharedMemorySize, GEMM_SMEM);

    __nv_bfloat16 *wtH = whi + 0*WSLOT, *wtL = wlo + 0*WSLOT;
    __nv_bfloat16 *wfH = whi + 1*WSLOT, *wfL = wlo + 1*WSLOT;
    __nv_bfloat16 *wbH = whi + 2*WSLOT, *wbL = wlo + 2*WSLOT;
    __nv_bfloat16 *wsH = whi + 3*WSLOT, *wsL = wlo + 3*WSLOT;
    __nv_bfloat16 *wTH = whi + 4*WSLOT, *wTL = wlo + 4*WSLOT;
    __nv_bfloat16 *wFH = whi + 5*WSLOT, *wFL = wlo + 5*WSLOT;

    // ---- Phase 0: split weights and x_time into bf16 hi/lo ----
    split_launch(wt_ih,  nullptr, wtH, wtL, (size_t)G3 * Dd);
    split_launch(wf_ih,  nullptr, wfH, wfL, (size_t)G3 * Dd);
    split_launch(wb_ih,  nullptr, wbH, wbL, (size_t)G3 * Dd);
    split_launch(ws_ih,  nullptr, wsH, wsL, (size_t)G3 * Dd);
    split_launch(W_time, nullptr, wTH, wTL, (size_t)Dd * G3);
    split_launch(W_freq, nullptr, wFH, wFL, (size_t)Dd * Dd);
    split_launch(x_time, nullptr, ahi, alo, (size_t)NT * Dd);

    // ---- Phase 1: input projections (tensor cores) ----
    {
        dim3 grid(G3 / 128, NT / 128);
        gemm_bf3<<<grid, blk, GEMM_SMEM>>>(ahi, alo, wtH, wtL, bt_ih, nullptr, gi_t, Dd, G3);
        gemm_bf3<<<grid, blk, GEMM_SMEM>>>(ahi, alo, wfH, wfL, bf_ih, nullptr, gi_f, Dd, G3);
        gemm_bf3<<<grid, blk, GEMM_SMEM>>>(ahi, alo, wbH, wbL, bb_ih, nullptr, gi_b, Dd, G3);
    }

    // ---- Phase 2: persistent time GRU scan ----
    cudaMemsetAsync(h0, 0, (size_t)NSEQ_T * Dd * sizeof(float));
    cudaMemsetAsync(h1, 0, (size_t)NSEQ_T * Dd * sizeof(float));
    cudaMemsetAsync(tbar, 0, TGROUPS * sizeof(unsigned));
    gru_time_persist<<<dim3(TGROUPS, TCOLB), blk, persist_smem>>>(
        gi_t, wt_hh, bt_hh, xcat, h0, h1);

    // ---- Phase 3: bidirectional freq GRU scan ----
    cudaMemsetAsync(h0, 0, (size_t)NSEQ_F * Dd * sizeof(float));
    cudaMemsetAsync(h2, 0, (size_t)NSEQ_F * Dd * sizeof(float));
    for (int s = 0; s < Mm; s++) {
        float* hpF = (s & 1) ? h1 : h0;
        float* hnF = (s & 1) ? h0 : h1;
        float* hpB = (s & 1) ? h3 : h2;
        float* hnB = (s & 1) ? h2 : h3;
        GruSet SF{hpF, hnF, gi_f, wf_hh, bf_hh, xcat, G3, Dd,      s};
        GruSet SB{hpB, hnB, gi_b, wb_hh, bb_hh, xcat, G3, 2 * Dd,  Mm - 1 - s};
        gru_step<32><<<dim3(NSEQ_F / 32, 16, 2), blk>>>(SF, SB, 0);
    }

    // ---- Phase 4: xt = xcat @ W_time^T + b_time + x_time (tensor cores) ----
    split_launch(xcat, nullptr, ahi, alo, (size_t)NT * G3);
    gemm_bf3<<<dim3(Dd / 128, NT / 128), blk, GEMM_SMEM>>>(
        ahi, alo, wTH, wTL, b_time, x_time, dout, G3, Dd);

    // ---- Phase 5: gi_s = (xt + x_freq) @ ws_ih^T + bs_ih ----
    split_launch(dout, x_freq, ahi, alo, (size_t)NT * Dd);
    gemm_bf3<<<dim3(G3 / 128, NT / 128), blk, GEMM_SMEM>>>(
        ahi, alo, wsH, wsL, bs_ih, nullptr, gi_s, Dd, G3);

    // ---- Phase 6: stack GRU scan ----
    cudaMemsetAsync(h0, 0, (size_t)NSEQ_F * Dd * sizeof(float));
    for (int s = 0; s < Mm; s++) {
        float* hp = (s & 1) ? h1 : h0;
        float* hn = (s & 1) ? h0 : h1;
        GruSet S{hp, hn, gi_s, ws_hh, bs_hh, xs, Dd, 0, s};
        gru_step<32><<<dim3(NSEQ_F / 32, 16, 1), blk>>>(S, S, 0);
    }

    // ---- Phase 7: xf = xs @ W_freq^T + b_freq + x_freq ----
    split_launch(xs, nullptr, ahi, alo, (size_t)NT * Dd);
    gemm_bf3<<<dim3(Dd / 128, NT / 128), blk, GEMM_SMEM>>>(
        ahi, alo, wFH, wFL, b_freq, x_freq, dout + (size_t)NT * Dd, Dd, Dd);
}

// round 6
// speedup vs baseline: 2.1256x; 1.2339x over previous
#include <cuda_runtime.h>
#include <cuda_bf16.h>
#include <cstdint>

// ---------------------------------------------------------------------------
// Problem constants
// ---------------------------------------------------------------------------
constexpr int Bb = 2, Tt = 256, Mm = 80, Dd = 512;
constexpr int NT = Bb * Tt * Mm;   // 40960 tokens
constexpr int G3 = 3 * Dd;         // 1536
constexpr int NSEQ_T = Bb * Mm;    // 160
constexpr int NSEQ_F = Bb * Tt;    // 512

constexpr int TGROUPS = 8;
constexpr int TSQ = NSEQ_T / TGROUPS;  // 20
constexpr int TCOLB = 16;

// ---------------------------------------------------------------------------
// Static device scratch
// ---------------------------------------------------------------------------
__device__ float g_gi_t[(size_t)NT * G3];
__device__ float g_gi_f[(size_t)NT * G3];
__device__ float g_gi_b[(size_t)NT * G3];
__device__ float g_gi_s[(size_t)NT * G3];
__device__ float g_h0[NSEQ_F * Dd];
__device__ float g_h1[NSEQ_F * Dd];
__device__ float g_h2[NSEQ_F * Dd];
__device__ float g_h3[NSEQ_F * Dd];
__device__ float g_gh[2 * (size_t)NSEQ_F * G3];       // per-step gh scratch
__device__ unsigned g_tbar[TGROUPS];

// bf16 split buffers (activations)
__device__ __nv_bfloat16 g_ahi[(size_t)NT * G3];
__device__ __nv_bfloat16 g_alo[(size_t)NT * G3];
// bf16 hidden-state ping-pong: [dir(2)*pp(2)][NSEQ_F*Dd]
__device__ __nv_bfloat16 g_hbhi[4 * NSEQ_F * Dd];
__device__ __nv_bfloat16 g_hblo[4 * NSEQ_F * Dd];
// weights: 9 slots of 1536*512
constexpr size_t WSLOT = 786432;
__device__ __nv_bfloat16 g_whi[9 * WSLOT];
__device__ __nv_bfloat16 g_wlo[9 * WSLOT];

// ---------------------------------------------------------------------------
// PTX helpers (portable: cp.async / ldmatrix / mma.sync)
// ---------------------------------------------------------------------------
__device__ __forceinline__ uint32_t smem_to_u32(const void* p) {
    uint32_t a;
    asm("{ .reg .u64 t; cvta.to.shared.u64 t, %1; cvt.u32.u64 %0, t; }"
        : "=r"(a) : "l"(p));
    return a;
}
#define CP_ASYNC16(dst, src) \
    asm volatile("cp.async.cg.shared.global [%0], [%1], 16;" \
        :: "r"((uint32_t)(dst)), "l"(src) : "memory")
#define CP_COMMIT() asm volatile("cp.async.commit_group;" ::: "memory")
#define CP_WAIT(n)  asm volatile("cp.async.wait_group %0;" :: "n"(n) : "memory")

__device__ __forceinline__ void ldsm4(uint32_t* r, uint32_t addr) {
    asm volatile("ldmatrix.sync.aligned.m8n8.x4.shared.b16 {%0,%1,%2,%3}, [%4];"
        : "=r"(r[0]), "=r"(r[1]), "=r"(r[2]), "=r"(r[3]) : "r"(addr));
}
__device__ __forceinline__ void mma16816(float* c, const uint32_t* a, const uint32_t* b) {
    asm volatile(
        "mma.sync.aligned.m16n8k16.row.col.f32.bf16.bf16.f32 "
        "{%0,%1,%2,%3}, {%4,%5,%6,%7}, {%8,%9}, {%0,%1,%2,%3};"
        : "+f"(c[0]), "+f"(c[1]), "+f"(c[2]), "+f"(c[3])
        : "r"(a[0]), "r"(a[1]), "r"(a[2]), "r"(a[3]), "r"(b[0]), "r"(b[1]));
}

// ---------------------------------------------------------------------------
// fp32 -> (hi,lo) bf16 split (optionally X+Y first)
// ---------------------------------------------------------------------------
__global__ void split_bf16_kernel(
    const float* __restrict__ X, const float* __restrict__ Y,
    __nv_bfloat16* __restrict__ hi, __nv_bfloat16* __restrict__ lo, int n4)
{
    int i = blockIdx.x * blockDim.x + threadIdx.x;
    if (i >= n4) return;
    float4 v = reinterpret_cast<const float4*>(X)[i];
    if (Y) {
        float4 y = reinterpret_cast<const float4*>(Y)[i];
        v.x += y.x; v.y += y.y; v.z += y.z; v.w += y.w;
    }
    __nv_bfloat16 h0 = __float2bfloat16_rn(v.x);
    __nv_bfloat16 h1 = __float2bfloat16_rn(v.y);
    __nv_bfloat16 h2 = __float2bfloat16_rn(v.z);
    __nv_bfloat16 h3 = __float2bfloat16_rn(v.w);
    __nv_bfloat16 l0 = __float2bfloat16_rn(v.x - __bfloat162float(h0));
    __nv_bfloat16 l1 = __float2bfloat16_rn(v.y - __bfloat162float(h1));
    __nv_bfloat16 l2 = __float2bfloat16_rn(v.z - __bfloat162float(h2));
    __nv_bfloat16 l3 = __float2bfloat16_rn(v.w - __bfloat162float(h3));
    reinterpret_cast<__nv_bfloat162*>(hi)[2*i]   = __nv_bfloat162(h0, h1);
    reinterpret_cast<__nv_bfloat162*>(hi)[2*i+1] = __nv_bfloat162(h2, h3);
    reinterpret_cast<__nv_bfloat162*>(lo)[2*i]   = __nv_bfloat162(l0, l1);
    reinterpret_cast<__nv_bfloat162*>(lo)[2*i+1] = __nv_bfloat162(l2, l3);
}

// ---------------------------------------------------------------------------
// mma.sync GEMM (3-product bf16 split): C = A @ B^T + bias (+ res)
// Block tile 128x128, BK=32, double-buffered cp.async.
// Dual-args: blockIdx.z selects g0/g1 (fused fwd/bwd recurrent steps).
// ---------------------------------------------------------------------------
constexpr int GSTRIDE = 40;
constexpr int TILE_B  = 128 * GSTRIDE * 2;
constexpr int STAGE_B = 4 * TILE_B;
constexpr int GEMM_SMEM = 2 * STAGE_B;   // 81920 B

struct GArgs {
    const __nv_bfloat16 *Ahi, *Alo, *Bhi, *Blo;
    const float *bias, *res;
    float *C;
};

__global__ __launch_bounds__(256, 1) void gemm_bf3(GArgs g0, GArgs g1, int K, int N)
{
    const GArgs g = blockIdx.z ? g1 : g0;
    extern __shared__ char smem[];
    const uint32_t sb = smem_to_u32(smem);
    const int tid  = threadIdx.x;
    const int lane = tid & 31;
    const int wid  = tid >> 5;
    const int wm   = wid & 3;
    const int wn   = wid >> 2;
    const int row0 = blockIdx.y * 128;
    const int col0 = blockIdx.x * 128;

    const __nv_bfloat16* srcs[4] = {g.Ahi, g.Alo, g.Bhi, g.Blo};

    auto stage_load = [&](int c, int buf) {
        const int k0 = c * 32;
        const uint32_t base = sb + buf * STAGE_B;
#pragma unroll
        for (int t4 = 0; t4 < 4; t4++) {
            const __nv_bfloat16* src = srcs[t4];
            const int rbase = (t4 < 2) ? row0 : col0;
#pragma unroll
            for (int i = 0; i < 2; i++) {
                int idx = tid + i * 256;
                int r = idx >> 2;
                int seg = idx & 3;
                uint32_t dst = base + t4 * TILE_B + r * (GSTRIDE * 2) + seg * 16;
                const void* gp = src + (size_t)(rbase + r) * K + k0 + seg * 8;
                CP_ASYNC16(dst, gp);
            }
        }
        CP_COMMIT();
    };

    float acc[2][8][4];
#pragma unroll
    for (int mf = 0; mf < 2; mf++)
#pragma unroll
        for (int nf = 0; nf < 8; nf++)
#pragma unroll
            for (int q = 0; q < 4; q++) acc[mf][nf][q] = 0.f;

    const int NC = K / 32;
    stage_load(0, 0);

    for (int c = 0; c < NC; c++) {
        const int buf = c & 1;
        if (c + 1 < NC) {
            stage_load(c + 1, buf ^ 1);
            CP_WAIT(1);
        } else {
            CP_WAIT(0);
        }
        __syncthreads();

        const uint32_t st = sb + buf * STAGE_B;
        const uint32_t a_off =
            ((wm * 32 + (lane & 15)) * GSTRIDE + ((lane >> 4) * 8)) * 2;
        const uint32_t b_row = wn * 64 + (lane & 7) + ((lane >> 4) & 1) * 8;
        const uint32_t b_off = (b_row * GSTRIDE + (((lane >> 3) & 1) * 8)) * 2;

#pragma unroll
        for (int kk = 0; kk < 2; kk++) {
            const uint32_t kb = kk * 32;
            uint32_t ahi[2][4], alo[2][4];
#pragma unroll
            for (int mf = 0; mf < 2; mf++) {
                ldsm4(ahi[mf], st + 0 * TILE_B + a_off + mf * 16 * (GSTRIDE * 2) + kb);
                ldsm4(alo[mf], st + 1 * TILE_B + a_off + mf * 16 * (GSTRIDE * 2) + kb);
            }
            uint32_t bhi[8][2], blo[8][2];
#pragma unroll
            for (int p = 0; p < 4; p++) {
                uint32_t r4[4];
                ldsm4(r4, st + 2 * TILE_B + b_off + p * 16 * (GSTRIDE * 2) + kb);
                bhi[2*p][0] = r4[0]; bhi[2*p][1] = r4[1];
                bhi[2*p+1][0] = r4[2]; bhi[2*p+1][1] = r4[3];
                ldsm4(r4, st + 3 * TILE_B + b_off + p * 16 * (GSTRIDE * 2) + kb);
                blo[2*p][0] = r4[0]; blo[2*p][1] = r4[1];
                blo[2*p+1][0] = r4[2]; blo[2*p+1][1] = r4[3];
            }
#pragma unroll
            for (int mf = 0; mf < 2; mf++)
#pragma unroll
                for (int nf = 0; nf < 8; nf++) {
                    mma16816(acc[mf][nf], ahi[mf], bhi[nf]);
                    mma16816(acc[mf][nf], alo[mf], bhi[nf]);
                    mma16816(acc[mf][nf], ahi[mf], blo[nf]);
                }
        }
        __syncthreads();
    }

#pragma unroll
    for (int mf = 0; mf < 2; mf++) {
        const int rA = row0 + wm * 32 + mf * 16 + (lane >> 2);
        const int rB = rA + 8;
#pragma unroll
        for (int nf = 0; nf < 8; nf++) {
            const int cc = col0 + wn * 64 + nf * 8 + (lane & 3) * 2;
            float2 v0, v1;
            v0.x = acc[mf][nf][0] + g.bias[cc];
            v0.y = acc[mf][nf][1] + g.bias[cc + 1];
            v1.x = acc[mf][nf][2] + g.bias[cc];
            v1.y = acc[mf][nf][3] + g.bias[cc + 1];
            if (g.res) {
                float2 r0 = *reinterpret_cast<const float2*>(g.res + (size_t)rA * N + cc);
                float2 r1 = *reinterpret_cast<const float2*>(g.res + (size_t)rB * N + cc);
                v0.x += r0.x; v0.y += r0.y; v1.x += r1.x; v1.y += r1.y;
            }
            *reinterpret_cast<float2*>(g.C + (size_t)rA * N + cc) = v0;
            *reinterpret_cast<float2*>(g.C + (size_t)rB * N + cc) = v1;
        }
    }
}

// ---------------------------------------------------------------------------
// Activation helpers
// ---------------------------------------------------------------------------
__device__ __forceinline__ float sigf(float x) {
    return 1.f / (1.f + __expf(-x));
}
__device__ __forceinline__ float tanhfast(float x) {
    float e2x = __expf(2.f * x);
    return 1.f - 2.f / (e2x + 1.f);
}

// ---------------------------------------------------------------------------
// Gate kernel for tensor-core recurrent steps.
// gh already includes b_hh (GEMM bias). Writes h (fp32 + bf16 hi/lo pair)
// and the scan output directly as bf16 hi/lo (GEMM-ready).
// ---------------------------------------------------------------------------
struct SArgs {
    const float* gh;          // [NSEQ_F][G3]
    const float* gi;          // [NT][G3]
    const float* hprev;       // [NSEQ_F][Dd] fp32
    float* hnext;
    __nv_bfloat16 *hhi, *hlo; // next-step GEMM operand
    __nv_bfloat16 *ohi, *olo; // output split buffers
    int outStride, outOff, mtok;
};

__global__ __launch_bounds__(256) void gate_step(SArgs a0, SArgs a1)
{
    const SArgs a = blockIdx.z ? a1 : a0;
    const int idx = blockIdx.x * 256 + threadIdx.x;   // 0 .. NSEQ_F*Dd-1
    const int s = idx >> 9;
    const int j = idx & 511;

    const float* ghr = a.gh + (size_t)s * G3;
    const int token = s * Mm + a.mtok;
    const float* gir = a.gi + (size_t)token * G3;

    float r = sigf(gir[j]        + ghr[j]);
    float z = sigf(gir[Dd + j]   + ghr[Dd + j]);
    float n = tanhfast(gir[2*Dd + j] + r * ghr[2*Dd + j]);
    float hp = a.hprev[idx];
    float hv = (1.f - z) * n + z * hp;

    a.hnext[idx] = hv;
    __nv_bfloat16 hi = __float2bfloat16_rn(hv);
    __nv_bfloat16 lo = __float2bfloat16_rn(hv - __bfloat162float(hi));
    a.hhi[idx] = hi;
    a.hlo[idx] = lo;
    size_t o = (size_t)token * a.outStride + a.outOff + j;
    a.ohi[o] = hi;
    a.olo[o] = lo;
}

// ---------------------------------------------------------------------------
// Persistent time-GRU scan — outputs written directly as bf16 hi/lo (xcat)
// ---------------------------------------------------------------------------
__global__ __launch_bounds__(256, 1) void gru_time_persist(
    const float* __restrict__ gi, const float* __restrict__ Whh,
    const float* __restrict__ bhh,
    __nv_bfloat16* __restrict__ ohi, __nv_bfloat16* __restrict__ olo,
    float* __restrict__ hb0, float* __restrict__ hb1)
{
    const int grp  = blockIdx.x;
    const int cb   = blockIdx.y;
    const int j0   = cb * 32;
    const int tid  = threadIdx.x;
    const int lane = tid & 31;
    const int w    = tid >> 5;
    const int k0   = w * 64;

    extern __shared__ float sm[];
    float* hs   = sm;
    float* part = sm + TSQ * 512;

    float wr[64], wz[64], wn[64];
    {
        const float* Wr = Whh + (size_t)(0 * Dd + j0 + lane) * Dd + k0;
        const float* Wz = Whh + (size_t)(1 * Dd + j0 + lane) * Dd + k0;
        const float* Wn = Whh + (size_t)(2 * Dd + j0 + lane) * Dd + k0;
#pragma unroll
        for (int i = 0; i < 64; i += 4) {
            float4 a = *reinterpret_cast<const float4*>(Wr + i);
            float4 b = *reinterpret_cast<const float4*>(Wz + i);
            float4 c = *reinterpret_cast<const float4*>(Wn + i);
            wr[i] = a.x; wr[i+1] = a.y; wr[i+2] = a.z; wr[i+3] = a.w;
            wz[i] = b.x; wz[i+1] = b.y; wz[i+2] = b.z; wz[i+3] = b.w;
            wn[i] = c.x; wn[i+1] = c.y; wn[i+2] = c.z; wn[i+3] = c.w;
        }
    }

    for (int t = 0; t < Tt; t++) {
        const float* hc = (t & 1) ? hb1 : hb0;
        float*       hn = (t & 1) ? hb0 : hb1;

        for (int i = tid; i < TSQ * 128; i += 256) {
            int s  = i >> 7;
            int k4 = i & 127;
            float4 v = __ldcg(reinterpret_cast<const float4*>(
                hc + (size_t)(grp * TSQ + s) * Dd) + k4);
            *reinterpret_cast<float4*>(hs + s * Dd + k4 * 4) = v;
        }
        __syncthreads();

        for (int s = 0; s < TSQ; s++) {
            float ar = 0.f, az = 0.f, an = 0.f;
            const float* hrow = hs + s * Dd + k0;
#pragma unroll
            for (int i = 0; i < 64; i += 4) {
                float4 h4 = *reinterpret_cast<const float4*>(hrow + i);
                ar = fmaf(h4.x, wr[i],   ar); az = fmaf(h4.x, wz[i],   az); an = fmaf(h4.x, wn[i],   an);
                ar = fmaf(h4.y, wr[i+1], ar); az = fmaf(h4.y, wz[i+1], az); an = fmaf(h4.y, wn[i+1], an);
                ar = fmaf(h4.z, wr[i+2], ar); az = fmaf(h4.z, wz[i+2], az); an = fmaf(h4.z, wn[i+2], an);
                ar = fmaf(h4.w, wr[i+3], ar); az = fmaf(h4.w, wz[i+3], az); an = fmaf(h4.w, wn[i+3], an);
            }
            part[((s * 3 + 0) * 32 + lane) * 8 + w] = ar;
            part[((s * 3 + 1) * 32 + lane) * 8 + w] = az;
            part[((s * 3 + 2) * 32 + lane) * 8 + w] = an;
        }
        __syncthreads();

        for (int idx = tid; idx < TSQ * 32; idx += 256) {
            int s = idx >> 5, j = idx & 31;
            float r = 0.f, z = 0.f, n = 0.f;
            const float* pr = part + ((s * 3 + 0) * 32 + j) * 8;
            const float* pz = part + ((s * 3 + 1) * 32 + j) * 8;
            const float* pn = part + ((s * 3 + 2) * 32 + j) * 8;
#pragma unroll
            for (int ww = 0; ww < 8; ww++) { r += pr[ww]; z += pz[ww]; n += pn[ww]; }

            int sg = grp * TSQ + s;
            int b  = sg / Mm;
            int m  = sg - b * Mm;
            size_t token = ((size_t)(b * Tt + t)) * Mm + m;
            const float* gir = gi + token * G3;
            int jc = j0 + j;
            float rr = sigf(gir[jc]        + r + bhh[jc]);
            float zz = sigf(gir[Dd + jc]   + z + bhh[Dd + jc]);
            float nn = tanhfast(gir[2*Dd + jc] + rr * (n + bhh[2*Dd + jc]));
            float hp = hs[s * Dd + jc];
            float hv = (1.f - zz) * nn + zz * hp;
            __stcg(hn + (size_t)sg * Dd + jc, hv);
            __nv_bfloat16 hib = __float2bfloat16_rn(hv);
            ohi[token * G3 + jc] = hib;
            olo[token * G3 + jc] = __float2bfloat16_rn(hv - __bfloat162float(hib));
        }

        __threadfence();
        __syncthreads();
        if (tid == 0) {
            atomicAdd(&g_tbar[grp], 1u);
            unsigned target = (unsigned)(t + 1) * TCOLB;
            while (atomicAdd(&g_tbar[grp], 0u) < target) {
                __nanosleep(64);
            }
        }
        __syncthreads();
    }
}

// ---------------------------------------------------------------------------
// Launch
// ---------------------------------------------------------------------------
static void split_launch(const float* X, const float* Y,
                         __nv_bfloat16* hi, __nv_bfloat16* lo, size_t n)
{
    int n4 = (int)(n / 4);
    split_bf16_kernel<<<(n4 + 255) / 256, 256>>>(X, Y, hi, lo, n4);
}

extern "C" void kernel_launch(void* const* d_in, const int* in_sizes, int n_in,
                              void* d_out_v, int out_size)
{
    const float* x_time = (const float*)d_in[0];
    const float* x_freq = (const float*)d_in[1];
    const float* wt_ih  = (const float*)d_in[2];
    const float* wt_hh  = (const float*)d_in[3];
    const float* bt_ih  = (const float*)d_in[4];
    const float* bt_hh  = (const float*)d_in[5];
    const float* wf_ih  = (const float*)d_in[6];
    const float* wf_hh  = (const float*)d_in[7];
    const float* bf_ih  = (const float*)d_in[8];
    const float* bf_hh  = (const float*)d_in[9];
    const float* wb_ih  = (const float*)d_in[10];
    const float* wb_hh  = (const float*)d_in[11];
    const float* bb_ih  = (const float*)d_in[12];
    const float* bb_hh  = (const float*)d_in[13];
    const float* ws_ih  = (const float*)d_in[14];
    const float* ws_hh  = (const float*)d_in[15];
    const float* bs_ih  = (const float*)d_in[16];
    const float* bs_hh  = (const float*)d_in[17];
    const float* W_time = (const float*)d_in[18];
    const float* b_time = (const float*)d_in[19];
    const float* W_freq = (const float*)d_in[20];
    const float* b_freq = (const float*)d_in[21];
    float* dout = (float*)d_out_v;

    float *gi_t, *gi_f, *gi_b, *gi_s, *h0, *h1, *h2, *h3, *gh;
    unsigned* tbar;
    __nv_bfloat16 *ahi, *alo, *whi, *wlo, *hbhi, *hblo;
    cudaGetSymbolAddress((void**)&gi_t, g_gi_t);
    cudaGetSymbolAddress((void**)&gi_f, g_gi_f);
    cudaGetSymbolAddress((void**)&gi_b, g_gi_b);
    cudaGetSymbolAddress((void**)&gi_s, g_gi_s);
    cudaGetSymbolAddress((void**)&h0,   g_h0);
    cudaGetSymbolAddress((void**)&h1,   g_h1);
    cudaGetSymbolAddress((void**)&h2,   g_h2);
    cudaGetSymbolAddress((void**)&h3,   g_h3);
    cudaGetSymbolAddress((void**)&gh,   g_gh);
    cudaGetSymbolAddress((void**)&tbar, g_tbar);
    cudaGetSymbolAddress((void**)&ahi,  g_ahi);
    cudaGetSymbolAddress((void**)&alo,  g_alo);
    cudaGetSymbolAddress((void**)&whi,  g_whi);
    cudaGetSymbolAddress((void**)&wlo,  g_wlo);
    cudaGetSymbolAddress((void**)&hbhi, g_hbhi);
    cudaGetSymbolAddress((void**)&hblo, g_hblo);

    const dim3 blk(256);
    const int persist_smem = (TSQ * 512 + TSQ * 3 * 32 * 8) * sizeof(float);
    cudaFuncSetAttribute(gru_time_persist,
                         cudaFuncAttributeMaxDynamicSharedMemorySize, persist_smem);
    cudaFuncSetAttribute(gemm_bf3,
                         cudaFuncAttributeMaxDynamicSharedMemorySize, GEMM_SMEM);

    __nv_bfloat16 *wtH = whi + 0*WSLOT, *wtL = wlo + 0*WSLOT;   // wt_ih
    __nv_bfloat16 *wfH = whi + 1*WSLOT, *wfL = wlo + 1*WSLOT;   // wf_ih
    __nv_bfloat16 *wbH = whi + 2*WSLOT, *wbL = wlo + 2*WSLOT;   // wb_ih
    __nv_bfloat16 *wsH = whi + 3*WSLOT, *wsL = wlo + 3*WSLOT;   // ws_ih
    __nv_bfloat16 *wTH = whi + 4*WSLOT, *wTL = wlo + 4*WSLOT;   // W_time
    __nv_bfloat16 *wFH = whi + 5*WSLOT, *wFL = wlo + 5*WSLOT;   // W_freq
    __nv_bfloat16 *wfhH = whi + 6*WSLOT, *wfhL = wlo + 6*WSLOT; // wf_hh
    __nv_bfloat16 *wbhH = whi + 7*WSLOT, *wbhL = wlo + 7*WSLOT; // wb_hh
    __nv_bfloat16 *wshH = whi + 8*WSLOT, *wshL = wlo + 8*WSLOT; // ws_hh

    const size_t HB = (size_t)NSEQ_F * Dd;   // 262144

    // ---- Phase 0: splits ----
    split_launch(wt_ih,  nullptr, wtH, wtL, (size_t)G3 * Dd);
    split_launch(wf_ih,  nullptr, wfH, wfL, (size_t)G3 * Dd);
    split_launch(wb_ih,  nullptr, wbH, wbL, (size_t)G3 * Dd);
    split_launch(ws_ih,  nullptr, wsH, wsL, (size_t)G3 * Dd);
    split_launch(W_time, nullptr, wTH, wTL, (size_t)Dd * G3);
    split_launch(W_freq, nullptr, wFH, wFL, (size_t)Dd * Dd);
    split_launch(wf_hh,  nullptr, wfhH, wfhL, (size_t)G3 * Dd);
    split_launch(wb_hh,  nullptr, wbhH, wbhL, (size_t)G3 * Dd);
    split_launch(ws_hh,  nullptr, wshH, wshL, (size_t)G3 * Dd);
    split_launch(x_time, nullptr, ahi, alo, (size_t)NT * Dd);

    // ---- Phase 1: input projections ----
    {
        dim3 grid(G3 / 128, NT / 128, 1);
        GArgs a{ahi, alo, wtH, wtL, bt_ih, nullptr, gi_t};
        gemm_bf3<<<grid, blk, GEMM_SMEM>>>(a, a, Dd, G3);
        GArgs b{ahi, alo, wfH, wfL, bf_ih, nullptr, gi_f};
        gemm_bf3<<<grid, blk, GEMM_SMEM>>>(b, b, Dd, G3);
        GArgs c{ahi, alo, wbH, wbL, bb_ih, nullptr, gi_b};
        gemm_bf3<<<grid, blk, GEMM_SMEM>>>(c, c, Dd, G3);
    }

    // ---- Phase 2: persistent time GRU scan (writes xcat cols [0,512) bf16) --
    cudaMemsetAsync(h0, 0, (size_t)NSEQ_T * Dd * sizeof(float));
    cudaMemsetAsync(h1, 0, (size_t)NSEQ_T * Dd * sizeof(float));
    cudaMemsetAsync(tbar, 0, TGROUPS * sizeof(unsigned));
    gru_time_persist<<<dim3(TGROUPS, TCOLB), blk, persist_smem>>>(
        gi_t, wt_hh, bt_hh, ahi, alo, h0, h1);

    // ---- Phase 3: bidirectional freq GRU scan (tensor cores per step) ----
    cudaMemsetAsync(h0, 0, HB * sizeof(float));
    cudaMemsetAsync(h2, 0, HB * sizeof(float));
    cudaMemsetAsync(hbhi + 0 * HB, 0, HB * sizeof(__nv_bfloat16));
    cudaMemsetAsync(hblo + 0 * HB, 0, HB * sizeof(__nv_bfloat16));
    cudaMemsetAsync(hbhi + 2 * HB, 0, HB * sizeof(__nv_bfloat16));
    cudaMemsetAsync(hblo + 2 * HB, 0, HB * sizeof(__nv_bfloat16));
    for (int s = 0; s < Mm; s++) {
        const int pp = s & 1;
        // gh[dir] = h_bf[dir] @ Whh[dir]^T + bhh[dir]
        GArgs gf{hbhi + (0 + pp) * HB, hblo + (0 + pp) * HB,
                 wfhH, wfhL, bf_hh, nullptr, gh};
        GArgs gb{hbhi + (2 + pp) * HB, hblo + (2 + pp) * HB,
                 wbhH, wbhL, bb_hh, nullptr, gh + (size_t)NSEQ_F * G3};
        gemm_bf3<<<dim3(G3 / 128, NSEQ_F / 128, 2), blk, GEMM_SMEM>>>(gf, gb, Dd, G3);

        float* hpF = pp ? h1 : h0;  float* hnF = pp ? h0 : h1;
        float* hpB = pp ? h3 : h2;  float* hnB = pp ? h2 : h3;
        SArgs sf{gh, gi_f, hpF, hnF,
                 hbhi + (0 + (pp ^ 1)) * HB, hblo + (0 + (pp ^ 1)) * HB,
                 ahi, alo, G3, Dd, s};
        SArgs sb{gh + (size_t)NSEQ_F * G3, gi_b, hpB, hnB,
                 hbhi + (2 + (pp ^ 1)) * HB, hblo + (2 + (pp ^ 1)) * HB,
                 ahi, alo, G3, 2 * Dd, Mm - 1 - s};
        gate_step<<<dim3((int)(HB / 256), 1, 2), blk>>>(sf, sb);
    }

    // ---- Phase 4: xt = xcat @ W_time^T + b_time + x_time ----
    {
        GArgs a{ahi, alo, wTH, wTL, b_time, x_time, dout};
        gemm_bf3<<<dim3(Dd / 128, NT / 128, 1), blk, GEMM_SMEM>>>(a, a, G3, Dd);
    }

    // ---- Phase 5: gi_s = (xt + x_freq) @ ws_ih^T + bs_ih ----
    split_launch(dout, x_freq, ahi, alo, (size_t)NT * Dd);
    {
        GArgs a{ahi, alo, wsH, wsL, bs_ih, nullptr, gi_s};
        gemm_bf3<<<dim3(G3 / 128, NT / 128, 1), blk, GEMM_SMEM>>>(a, a, Dd, G3);
    }

    // ---- Phase 6: stack GRU scan (tensor cores per step) ----
    cudaMemsetAsync(h0, 0, HB * sizeof(float));
    cudaMemsetAsync(hbhi + 0 * HB, 0, HB * sizeof(__nv_bfloat16));
    cudaMemsetAsync(hblo + 0 * HB, 0, HB * sizeof(__nv_bfloat16));
    for (int s = 0; s < Mm; s++) {
        const int pp = s & 1;
        GArgs ga{hbhi + pp * HB, hblo + pp * HB, wshH, wshL, bs_hh, nullptr, gh};
        gemm_bf3<<<dim3(G3 / 128, NSEQ_F / 128, 1), blk, GEMM_SMEM>>>(ga, ga, Dd, G3);

        float* hp = pp ? h1 : h0;  float* hn = pp ? h0 : h1;
        SArgs sa{gh, gi_s, hp, hn,
                 hbhi + (pp ^ 1) * HB, hblo + (pp ^ 1) * HB,
                 ahi, alo, Dd, 0, s};
        gate_step<<<dim3((int)(HB / 256), 1, 1), blk>>>(sa, sa);
    }

    // ---- Phase 7: xf = xs @ W_freq^T + b_freq + x_freq ----
    {
        GArgs a{ahi, alo, wFH, wFL, b_freq, x_freq, dout + (size_t)NT * Dd};
        gemm_bf3<<<dim3(Dd / 128, NT / 128, 1), blk, GEMM_SMEM>>>(a, a, Dd, Dd);
    }
}